// round 6
// baseline (speedup 1.0000x reference)
#include <cuda_runtime.h>

// Problem constants (fixed by the reference):
//   N_NODES = 2048, N_ELEMS = 4096
//   Output: (N + 2E) x (2E + N) = 10240 x 10240 fp32
#define NN 2048
#define EE 4096
#define WW (2 * EE + NN)   // 10240
#define W4 (WW / 4)        // 2560

// Virtual work items: 10 strips per output row (fill), then 32x32 transpose tiles.
#define STRIPS_PER_ROW 10
#define NUM_FILL_ITEMS (STRIPS_PER_ROW * WW)          // 102400
#define TP_TILES_X (EE / 32)                          // 128
#define TP_TILES_Y (NN / 32)                          // 64
#define NUM_TP_ITEMS (TP_TILES_X * TP_TILES_Y)        // 8192
#define NUM_ITEMS (NUM_FILL_ITEMS + NUM_TP_ITEMS)     // 110592

// Persistent launch: 8 CTAs/SM x 148 SMs
#define NUM_BLOCKS (148 * 8)                          // 1184

__global__ void __launch_bounds__(256) fused_kernel(
    const float* __restrict__ M,
    const float* __restrict__ params,
    const int* __restrict__ kinds,
    float* __restrict__ out)
{
    const int tid = threadIdx.x;
    __shared__ float tile[32][33];   // transpose staging [n_local][e_local]

    for (int v = blockIdx.x; v < NUM_ITEMS; v += NUM_BLOCKS) {
        if (v < NUM_FILL_ITEMS) {
            // --------------------------------------------------------------
            // FILL item: row = v / 10, strip = v % 10. One float4 per thread.
            // --------------------------------------------------------------
            const int row   = v / STRIPS_PER_ROW;
            const int strip = v - row * STRIPS_PER_ROW;
            const int c4    = strip * 256 + tid;       // 0 .. 2559
            const int col   = c4 * 4;

            float4 val = make_float4(0.f, 0.f, 0.f, 0.f);
            bool do_store = true;

            if (row < NN) {
                // kcl rows: [ M | 0 ]
                if (col < EE) {
                    val = reinterpret_cast<const float4*>(M)[row * (EE / 4) + c4];
                }
            } else if (row < NN + EE) {
                // kvl rows: [ 0 | I_E | -M^T ]  (-M^T written by tp items)
                if (col >= 2 * EE) {
                    do_store = false;
                } else {
                    const int r = row - NN;
                    const int d = EE + r;      // identity column
                    if (d >= col && d < col + 4) {
                        reinterpret_cast<float*>(&val)[d - col] = 1.0f;
                    }
                }
            } else {
                // elem rows: z diag at col=pos, y diag at col=E+pos
                const int pos = row - NN - EE;
                const int yc  = EE + pos;
                if (pos >= col && pos < col + 4) {
                    const float p = params[pos];
                    const int   k = kinds[pos];
                    float z = 0.0f;
                    if (k == 0)                      z = -p;   // R
                    else if (k == 2)                 z = 1.0f; // VC
                    else if (k == 3 && !(p > 0.0f))  z = 1.0f; // SW off
                    reinterpret_cast<float*>(&val)[pos - col] = z;
                }
                if (yc >= col && yc < col + 4) {
                    const float p = params[pos];
                    const int   k = kinds[pos];
                    const float y = (k == 0 || k == 1 || (k == 3 && p > 0.0f)) ? 1.0f : 0.0f;
                    reinterpret_cast<float*>(&val)[yc - col] = y;
                }
            }

            if (do_store) {
                reinterpret_cast<float4*>(out)[(long)row * W4 + c4] = val;
            }
        } else {
            // --------------------------------------------------------------
            // TRANSPOSE item: out[NN + e][2*EE + n] = -M[n][e], 32x32 tile.
            // --------------------------------------------------------------
            const int t  = v - NUM_FILL_ITEMS;
            const int et = t % TP_TILES_X;
            const int nt = t / TP_TILES_X;
            const int e0 = et * 32;
            const int n0 = nt * 32;

            // Load: one float4 per thread (32 rows x 8 float4/row)
            {
                const int lrow = tid >> 3;          // n_local 0..31
                const int lc4  = tid & 7;           // e_local/4 0..7
                const float4 m4 = reinterpret_cast<const float4*>(
                    M + (n0 + lrow) * EE + e0)[lc4];
                tile[lrow][lc4 * 4 + 0] = m4.x;
                tile[lrow][lc4 * 4 + 1] = m4.y;
                tile[lrow][lc4 * 4 + 2] = m4.z;
                tile[lrow][lc4 * 4 + 3] = m4.w;
            }
            __syncthreads();

            // Store: one float4 per thread. orow=e_local, oc4=n_local/4
            {
                const int orow = tid >> 3;
                const int oc4  = tid & 7;
                const int nl   = oc4 * 4;
                float4 val;
                val.x = -tile[nl + 0][orow];
                val.y = -tile[nl + 1][orow];
                val.z = -tile[nl + 2][orow];
                val.w = -tile[nl + 3][orow];
                reinterpret_cast<float4*>(
                    out + (long)(NN + e0 + orow) * WW + 2 * EE + n0)[oc4] = val;
            }
            __syncthreads();   // tile reused next iteration
        }
    }
}

extern "C" void kernel_launch(void* const* d_in, const int* in_sizes, int n_in,
                              void* d_out, int out_size)
{
    const float* M      = (const float*)d_in[0];
    const float* params = (const float*)d_in[1];
    const int*   kinds  = (const int*)d_in[2];
    float*       out    = (float*)d_out;

    (void)in_sizes; (void)n_in; (void)out_size;

    fused_kernel<<<NUM_BLOCKS, 256>>>(M, params, kinds, out);
}

// round 7
// speedup vs baseline: 1.1397x; 1.1397x over previous
#include <cuda_runtime.h>

// Problem constants (fixed by the reference):
//   N_NODES = 2048, N_ELEMS = 4096
//   Output: (N + 2E) x (2E + N) = 10240 x 10240 fp32
#define NN 2048
#define EE 4096
#define WW (2 * EE + NN)   // 10240
#define W4 (WW / 4)        // 2560

// Fill work: 10 strips (256 float4) per output row.
#define STRIPS_PER_ROW 10
#define NUM_FILL_ITEMS (STRIPS_PER_ROW * WW)          // 102400
// Transpose work: 32x32 tiles over the E x N (-M^T) block.
#define TP_TILES_X (EE / 32)                          // 128
#define TP_TILES_Y (NN / 32)                          // 64
#define NUM_TP_ITEMS (TP_TILES_X * TP_TILES_Y)        // 8192

// Interleave: every 13th block (bid % 13 == 12) is a transpose tile, so each
// resident wave carries ~8% transpose work mixed into the fill store stream.
// Grid sized so fill indices cover exactly [0, NUM_FILL_ITEMS):
//   fill_idx = bid - bid/13, max fill bid = 110932 -> grid = 110933.
#define TOTAL_BLOCKS 110933

__global__ void __launch_bounds__(256) fused_kernel(
    const float* __restrict__ M,
    const float* __restrict__ params,
    const int* __restrict__ kinds,
    float* __restrict__ out)
{
    const int bid = blockIdx.x;
    const int tid = threadIdx.x;

    const int q = bid / 13;
    const int r = bid - q * 13;

    if (r != 12) {
        // ------------------------------------------------------------------
        // FILL path (identical to R2 best): one float4 per thread.
        // ------------------------------------------------------------------
        const int f    = bid - q;                    // 0 .. NUM_FILL_ITEMS-1
        const int row  = f / STRIPS_PER_ROW;
        const int cblk = f - row * STRIPS_PER_ROW;
        const int c4   = cblk * 256 + tid;           // 0 .. 2559
        const int col  = c4 * 4;

        float4 v = make_float4(0.f, 0.f, 0.f, 0.f);

        if (row < NN) {
            // kcl rows: [ M | 0 ]
            if (col < EE) {
                v = reinterpret_cast<const float4*>(M)[row * (EE / 4) + c4];
            }
        } else if (row < NN + EE) {
            // kvl rows: [ 0 | I_E | -M^T ]
            if (col >= 2 * EE) return;   // -M^T written by transpose blocks
            const int rr = row - NN;
            if (col >= EE) {
                const int d = EE + rr;   // column of the identity 1
                if (d >= col && d < col + 4) {
                    reinterpret_cast<float*>(&v)[d - col] = 1.0f;
                }
            }
        } else {
            // elem rows: z diag at col=pos, y diag at col=E+pos
            const int pos = row - NN - EE;
            const int yc  = EE + pos;
            if (pos >= col && pos < col + 4) {
                const float p = params[pos];
                const int   k = kinds[pos];
                float z = 0.0f;
                if (k == 0)                      z = -p;   // R
                else if (k == 2)                 z = 1.0f; // VC
                else if (k == 3 && !(p > 0.0f))  z = 1.0f; // SW off
                reinterpret_cast<float*>(&v)[pos - col] = z;
            }
            if (yc >= col && yc < col + 4) {
                const float p = params[pos];
                const int   k = kinds[pos];
                const float y = (k == 0 || k == 1 || (k == 3 && p > 0.0f)) ? 1.0f : 0.0f;
                reinterpret_cast<float*>(&v)[yc - col] = y;
            }
        }

        reinterpret_cast<float4*>(out)[row * W4 + c4] = v;
    } else {
        // ------------------------------------------------------------------
        // TRANSPOSE path: out[NN + e][2*EE + n] = -M[n][e], 32x32 tile q.
        // ------------------------------------------------------------------
        const int t = q;
        if (t >= NUM_TP_ITEMS) return;

        __shared__ float tile[32][33];   // [n_local][e_local]

        const int et = t % TP_TILES_X;
        const int nt = t / TP_TILES_X;
        const int e0 = et * 32;
        const int n0 = nt * 32;

        // Load: one float4 per thread (32 rows x 8 float4/row), coalesced.
        {
            const int lrow = tid >> 3;          // n_local 0..31
            const int lc4  = tid & 7;           // e_local/4 0..7
            const float4 m4 = reinterpret_cast<const float4*>(
                M + (n0 + lrow) * EE + e0)[lc4];
            tile[lrow][lc4 * 4 + 0] = m4.x;
            tile[lrow][lc4 * 4 + 1] = m4.y;
            tile[lrow][lc4 * 4 + 2] = m4.z;
            tile[lrow][lc4 * 4 + 3] = m4.w;
        }
        __syncthreads();

        // Store: one float4 per thread, coalesced. orow=e_local, oc4=n_local/4
        {
            const int orow = tid >> 3;
            const int oc4  = tid & 7;
            const int nl   = oc4 * 4;
            float4 v;
            v.x = -tile[nl + 0][orow];
            v.y = -tile[nl + 1][orow];
            v.z = -tile[nl + 2][orow];
            v.w = -tile[nl + 3][orow];
            reinterpret_cast<float4*>(
                out + (NN + e0 + orow) * WW + 2 * EE + n0)[oc4] = v;
        }
    }
}

extern "C" void kernel_launch(void* const* d_in, const int* in_sizes, int n_in,
                              void* d_out, int out_size)
{
    const float* M      = (const float*)d_in[0];
    const float* params = (const float*)d_in[1];
    const int*   kinds  = (const int*)d_in[2];
    float*       out    = (float*)d_out;

    (void)in_sizes; (void)n_in; (void)out_size;

    fused_kernel<<<TOTAL_BLOCKS, 256>>>(M, params, kinds, out);
}

// round 8
// speedup vs baseline: 1.1602x; 1.0180x over previous
#include <cuda_runtime.h>

// Problem constants (fixed by the reference):
//   N_NODES = 2048, N_ELEMS = 4096
//   Output: (N + 2E) x (2E + N) = 10240 x 10240 fp32
#define NN 2048
#define EE 4096
#define WW (2 * EE + NN)   // 10240
#define W4 (WW / 4)        // 2560

// Fill work: 10 strips (256 float4) per output row. Strips covering the M
// block (kcl cols [0,E)) early-return: the tile blocks write those bytes.
#define STRIPS_PER_ROW 10
#define NUM_FILL_ITEMS (STRIPS_PER_ROW * WW)          // 102400
// Copy+transpose tiles: 32x32 over M. Each writes BOTH the kcl copy position
// and the -M^T position (single read of M, two coalesced writes).
#define TP_TILES_X (EE / 32)                          // 128 (e tiles)
#define TP_TILES_Y (NN / 32)                          // 64  (n tiles)
#define NUM_TP_ITEMS (TP_TILES_X * TP_TILES_Y)        // 8192
#define TOTAL_BLOCKS (NUM_FILL_ITEMS + NUM_TP_ITEMS)  // 110592

__global__ void __launch_bounds__(256) fused_kernel(
    const float* __restrict__ M,
    const float* __restrict__ params,
    const int* __restrict__ kinds,
    float* __restrict__ out)
{
    const int bid = blockIdx.x;
    const int tid = threadIdx.x;

    if (bid < NUM_FILL_ITEMS) {
        // ------------------------------------------------------------------
        // FILL path: pure zero/diag writes (no global loads in hot paths).
        // ------------------------------------------------------------------
        const int row  = bid / STRIPS_PER_ROW;
        const int cblk = bid - row * STRIPS_PER_ROW;
        const int c4   = cblk * 256 + tid;           // 0 .. 2559
        const int col  = c4 * 4;

        float4 v = make_float4(0.f, 0.f, 0.f, 0.f);

        if (row < NN) {
            // kcl rows: [ M | 0 ].  M block written by tile blocks.
            if (col < EE) return;
            // col >= EE -> zeros
        } else if (row < NN + EE) {
            // kvl rows: [ 0 | I_E | -M^T ].  -M^T written by tile blocks.
            if (col >= 2 * EE) return;
            const int rr = row - NN;
            if (col >= EE) {
                const int d = EE + rr;   // identity column
                if (d >= col && d < col + 4) {
                    reinterpret_cast<float*>(&v)[d - col] = 1.0f;
                }
            }
        } else {
            // elem rows: z diag at col=pos, y diag at col=E+pos
            const int pos = row - NN - EE;
            const int yc  = EE + pos;
            if (pos >= col && pos < col + 4) {
                const float p = params[pos];
                const int   k = kinds[pos];
                float z = 0.0f;
                if (k == 0)                      z = -p;   // R
                else if (k == 2)                 z = 1.0f; // VC
                else if (k == 3 && !(p > 0.0f))  z = 1.0f; // SW off
                reinterpret_cast<float*>(&v)[pos - col] = z;
            }
            if (yc >= col && yc < col + 4) {
                const float p = params[pos];
                const int   k = kinds[pos];
                const float y = (k == 0 || k == 1 || (k == 3 && p > 0.0f)) ? 1.0f : 0.0f;
                reinterpret_cast<float*>(&v)[yc - col] = y;
            }
        }

        reinterpret_cast<float4*>(out)[row * W4 + c4] = v;
    } else {
        // ------------------------------------------------------------------
        // COPY+TRANSPOSE tile: read M 32x32 tile ONCE, write it to the kcl
        // copy position AND (negated, transposed) to the -M^T position.
        //   copy : out[n][e]            = M[n][e]
        //   trans: out[NN + e][2E + n]  = -M[n][e]
        // ------------------------------------------------------------------
        __shared__ float tile[32][33];   // [n_local][e_local]

        const int t  = bid - NUM_FILL_ITEMS;
        const int et = t % TP_TILES_X;
        const int nt = t / TP_TILES_X;
        const int e0 = et * 32;
        const int n0 = nt * 32;

        // Load one float4 per thread (32 rows x 8 float4/row), coalesced.
        const int lrow = tid >> 3;          // n_local 0..31
        const int lc4  = tid & 7;           // e_local/4 0..7
        const float4 m4 = reinterpret_cast<const float4*>(
            M + (n0 + lrow) * EE + e0)[lc4];

        // (b) kcl copy store — straight from registers, coalesced.
        reinterpret_cast<float4*>(out)[(n0 + lrow) * W4 + (e0 >> 2) + lc4] = m4;

        // (c) stage for transpose.
        tile[lrow][lc4 * 4 + 0] = m4.x;
        tile[lrow][lc4 * 4 + 1] = m4.y;
        tile[lrow][lc4 * 4 + 2] = m4.z;
        tile[lrow][lc4 * 4 + 3] = m4.w;
        __syncthreads();

        // Transposed store: one float4 per thread, coalesced.
        const int orow = tid >> 3;          // e_local 0..31
        const int oc4  = tid & 7;           // n_local/4 0..7
        const int nl   = oc4 * 4;
        float4 v;
        v.x = -tile[nl + 0][orow];
        v.y = -tile[nl + 1][orow];
        v.z = -tile[nl + 2][orow];
        v.w = -tile[nl + 3][orow];
        reinterpret_cast<float4*>(
            out + (NN + e0 + orow) * WW + 2 * EE + n0)[oc4] = v;
    }
}

extern "C" void kernel_launch(void* const* d_in, const int* in_sizes, int n_in,
                              void* d_out, int out_size)
{
    const float* M      = (const float*)d_in[0];
    const float* params = (const float*)d_in[1];
    const int*   kinds  = (const int*)d_in[2];
    float*       out    = (float*)d_out;

    (void)in_sizes; (void)n_in; (void)out_size;

    fused_kernel<<<TOTAL_BLOCKS, 256>>>(M, params, kinds, out);
}

// round 9
// speedup vs baseline: 1.2645x; 1.0899x over previous
#include <cuda_runtime.h>

// Problem constants (fixed by the reference):
//   N_NODES = 2048, N_ELEMS = 4096
//   Output: (N + 2E) x (2E + N) = 10240 x 10240 fp32
#define NN 2048
#define EE 4096
#define WW (2 * EE + NN)   // 10240
#define W4 (WW / 4)        // 2560

// Fill: one block per output row (plain float4 stores, multiple per thread).
#define NUM_FILL_BLOCKS WW                            // 10240
// Copy+transpose tiles: 32x32 over M; each writes the kcl copy AND -M^T.
#define TP_TILES_X (EE / 32)                          // 128 (e tiles)
#define TP_TILES_Y (NN / 32)                          // 64  (n tiles)
#define NUM_TP_ITEMS (TP_TILES_X * TP_TILES_Y)        // 8192
#define TOTAL_BLOCKS (NUM_FILL_BLOCKS + NUM_TP_ITEMS) // 18432

__global__ void __launch_bounds__(256) fused_kernel(
    const float* __restrict__ M,
    const float* __restrict__ params,
    const int* __restrict__ kinds,
    float* __restrict__ out)
{
    const int bid = blockIdx.x;
    const int tid = threadIdx.x;

    if (bid < NUM_FILL_BLOCKS) {
        // ------------------------------------------------------------------
        // FILL path: this block owns output row `bid`. Thread t writes
        // c4 = t + 256*i. Plain (cached) float4 stores — NO __stcs.
        // ------------------------------------------------------------------
        const int row = bid;
        float4* orow4 = reinterpret_cast<float4*>(out) + (long)row * W4;
        const float4 zero4 = make_float4(0.f, 0.f, 0.f, 0.f);

        if (row < NN) {
            // kcl: [ M | 0 ]. M block (c4 < 1024, i=0..3) written by tiles.
            #pragma unroll
            for (int i = 4; i < 10; i++) {
                orow4[tid + 256 * i] = zero4;
            }
        } else if (row < NN + EE) {
            // kvl: [ 0 | I_E | (-M^T by tiles) ]. Write c4 in [0,2048): i=0..7.
            const int r   = row - NN;
            const int d   = EE + r;          // identity column
            const int dc4 = d >> 2;
            const int dl  = d & 3;
            #pragma unroll
            for (int i = 0; i < 8; i++) {
                const int c4 = tid + 256 * i;
                float4 v = zero4;
                if (c4 == dc4) reinterpret_cast<float*>(&v)[dl] = 1.0f;
                orow4[c4] = v;
            }
        } else {
            // elem: zeros + z diag at col=pos, y diag at col=E+pos.
            const int pos = row - NN - EE;
            const float p = params[pos];
            const int   k = kinds[pos];
            float z = 0.0f;
            if (k == 0)                      z = -p;   // R
            else if (k == 2)                 z = 1.0f; // VC
            else if (k == 3 && !(p > 0.0f))  z = 1.0f; // SW off
            const float y = (k == 0 || k == 1 || (k == 3 && p > 0.0f)) ? 1.0f : 0.0f;

            const int zc4 = pos >> 2;
            const int yc4 = (EE + pos) >> 2;
            const int l   = pos & 3;         // same sub-lane for both diags

            #pragma unroll
            for (int i = 0; i < 10; i++) {
                const int c4 = tid + 256 * i;
                float4 v = zero4;
                if (c4 == zc4) reinterpret_cast<float*>(&v)[l] = z;
                if (c4 == yc4) reinterpret_cast<float*>(&v)[l] = y;
                orow4[c4] = v;
            }
        }
    } else {
        // ------------------------------------------------------------------
        // COPY+TRANSPOSE tile (identical to R8): read M 32x32 tile once,
        //   copy : out[n][e]           = M[n][e]
        //   trans: out[NN + e][2E + n] = -M[n][e]
        // ------------------------------------------------------------------
        __shared__ float tile[32][33];   // [n_local][e_local]

        const int t  = bid - NUM_FILL_BLOCKS;
        const int et = t % TP_TILES_X;
        const int nt = t / TP_TILES_X;
        const int e0 = et * 32;
        const int n0 = nt * 32;

        // Coalesced float4 load (32 rows x 8 float4/row).
        const int lrow = tid >> 3;          // n_local 0..31
        const int lc4  = tid & 7;           // e_local/4 0..7
        const float4 m4 = reinterpret_cast<const float4*>(
            M + (n0 + lrow) * EE + e0)[lc4];

        // kcl copy store — straight from registers, coalesced.
        reinterpret_cast<float4*>(out)[(long)(n0 + lrow) * W4 + (e0 >> 2) + lc4] = m4;

        // Stage for transpose.
        tile[lrow][lc4 * 4 + 0] = m4.x;
        tile[lrow][lc4 * 4 + 1] = m4.y;
        tile[lrow][lc4 * 4 + 2] = m4.z;
        tile[lrow][lc4 * 4 + 3] = m4.w;
        __syncthreads();

        // Transposed store, coalesced.
        const int orow = tid >> 3;          // e_local 0..31
        const int oc4  = tid & 7;           // n_local/4 0..7
        const int nl   = oc4 * 4;
        float4 v;
        v.x = -tile[nl + 0][orow];
        v.y = -tile[nl + 1][orow];
        v.z = -tile[nl + 2][orow];
        v.w = -tile[nl + 3][orow];
        reinterpret_cast<float4*>(
            out + (long)(NN + e0 + orow) * WW + 2 * EE + n0)[oc4] = v;
    }
}

extern "C" void kernel_launch(void* const* d_in, const int* in_sizes, int n_in,
                              void* d_out, int out_size)
{
    const float* M      = (const float*)d_in[0];
    const float* params = (const float*)d_in[1];
    const int*   kinds  = (const int*)d_in[2];
    float*       out    = (float*)d_out;

    (void)in_sizes; (void)n_in; (void)out_size;

    fused_kernel<<<TOTAL_BLOCKS, 256>>>(M, params, kinds, out);
}

// round 10
// speedup vs baseline: 1.2651x; 1.0005x over previous
#include <cuda_runtime.h>

// Problem constants (fixed by the reference):
//   N_NODES = 2048, N_ELEMS = 4096
//   Output: (N + 2E) x (2E + N) = 10240 x 10240 fp32
#define NN 2048
#define EE 4096
#define WW (2 * EE + NN)   // 10240
#define W4 (WW / 4)        // 2560

// Fill: one block per output row (plain float4 stores, multiple per thread).
#define NUM_FILL_BLOCKS WW                            // 10240
// Copy+transpose tiles: 64x64 over M; each writes the kcl copy AND -M^T.
#define TP_TILE 64
#define TP_TILES_X (EE / TP_TILE)                     // 64 (e tiles)
#define TP_TILES_Y (NN / TP_TILE)                     // 32 (n tiles)
#define NUM_TP_ITEMS (TP_TILES_X * TP_TILES_Y)        // 2048
#define TOTAL_BLOCKS (NUM_FILL_BLOCKS + NUM_TP_ITEMS) // 12288

__global__ void __launch_bounds__(256) fused_kernel(
    const float* __restrict__ M,
    const float* __restrict__ params,
    const int* __restrict__ kinds,
    float* __restrict__ out)
{
    const int bid = blockIdx.x;
    const int tid = threadIdx.x;

    if (bid < NUM_FILL_BLOCKS) {
        // ------------------------------------------------------------------
        // FILL path (unchanged from R9 win): block owns output row `bid`.
        // Thread t writes c4 = t + 256*i. Plain cached float4 stores.
        // ------------------------------------------------------------------
        const int row = bid;
        float4* orow4 = reinterpret_cast<float4*>(out) + (long)row * W4;
        const float4 zero4 = make_float4(0.f, 0.f, 0.f, 0.f);

        if (row < NN) {
            // kcl: [ M | 0 ]. M block (i=0..3) written by tile blocks.
            #pragma unroll
            for (int i = 4; i < 10; i++) {
                orow4[tid + 256 * i] = zero4;
            }
        } else if (row < NN + EE) {
            // kvl: [ 0 | I_E | (-M^T by tiles) ]. Write c4 in [0,2048): i=0..7.
            const int r   = row - NN;
            const int d   = EE + r;          // identity column
            const int dc4 = d >> 2;
            const int dl  = d & 3;
            #pragma unroll
            for (int i = 0; i < 8; i++) {
                const int c4 = tid + 256 * i;
                float4 v = zero4;
                if (c4 == dc4) reinterpret_cast<float*>(&v)[dl] = 1.0f;
                orow4[c4] = v;
            }
        } else {
            // elem: zeros + z diag at col=pos, y diag at col=E+pos.
            const int pos = row - NN - EE;
            const float p = params[pos];
            const int   k = kinds[pos];
            float z = 0.0f;
            if (k == 0)                      z = -p;   // R
            else if (k == 2)                 z = 1.0f; // VC
            else if (k == 3 && !(p > 0.0f))  z = 1.0f; // SW off
            const float y = (k == 0 || k == 1 || (k == 3 && p > 0.0f)) ? 1.0f : 0.0f;

            const int zc4 = pos >> 2;
            const int yc4 = (EE + pos) >> 2;
            const int l   = pos & 3;         // same sub-lane for both diags

            #pragma unroll
            for (int i = 0; i < 10; i++) {
                const int c4 = tid + 256 * i;
                float4 v = zero4;
                if (c4 == zc4) reinterpret_cast<float*>(&v)[l] = z;
                if (c4 == yc4) reinterpret_cast<float*>(&v)[l] = y;
                orow4[c4] = v;
            }
        }
    } else {
        // ------------------------------------------------------------------
        // COPY+TRANSPOSE tile, 64x64: read M tile once (4 independent
        // float4 loads per thread, MLP=4), write the kcl copy straight from
        // registers, and the -M^T block via smem transpose.
        //   copy : out[n][e]           = M[n][e]
        //   trans: out[NN + e][2E + n] = -M[n][e]
        // ------------------------------------------------------------------
        __shared__ float tile[TP_TILE][TP_TILE + 1];   // [n_local][e_local]

        const int t  = bid - NUM_FILL_BLOCKS;
        const int et = t % TP_TILES_X;
        const int nt = t / TP_TILES_X;
        const int e0 = et * TP_TILE;
        const int n0 = nt * TP_TILE;

        // Batch all 4 loads first (independent -> 4 outstanding LDG.128).
        float4 m4[4];
        #pragma unroll
        for (int j = 0; j < 4; j++) {
            const int idx  = tid + 256 * j;
            const int lrow = idx >> 4;        // n_local 0..63
            const int lc4  = idx & 15;        // e_local/4 0..15
            m4[j] = reinterpret_cast<const float4*>(
                M + (long)(n0 + lrow) * EE + e0)[lc4];
        }

        // kcl copy stores — straight from registers, coalesced.
        #pragma unroll
        for (int j = 0; j < 4; j++) {
            const int idx  = tid + 256 * j;
            const int lrow = idx >> 4;
            const int lc4  = idx & 15;
            reinterpret_cast<float4*>(
                out)[(long)(n0 + lrow) * W4 + (e0 >> 2) + lc4] = m4[j];
        }

        // Stage for transpose.
        #pragma unroll
        for (int j = 0; j < 4; j++) {
            const int idx  = tid + 256 * j;
            const int lrow = idx >> 4;
            const int lc4  = idx & 15;
            tile[lrow][lc4 * 4 + 0] = m4[j].x;
            tile[lrow][lc4 * 4 + 1] = m4[j].y;
            tile[lrow][lc4 * 4 + 2] = m4[j].z;
            tile[lrow][lc4 * 4 + 3] = m4[j].w;
        }
        __syncthreads();

        // Transposed stores: 4 coalesced float4 per thread.
        #pragma unroll
        for (int j = 0; j < 4; j++) {
            const int idx  = tid + 256 * j;
            const int orow = idx >> 4;        // e_local 0..63
            const int oc4  = idx & 15;        // n_local/4 0..15
            const int nl   = oc4 * 4;
            float4 v;
            v.x = -tile[nl + 0][orow];
            v.y = -tile[nl + 1][orow];
            v.z = -tile[nl + 2][orow];
            v.w = -tile[nl + 3][orow];
            reinterpret_cast<float4*>(
                out + (long)(NN + e0 + orow) * WW + 2 * EE + n0)[oc4] = v;
        }
    }
}

extern "C" void kernel_launch(void* const* d_in, const int* in_sizes, int n_in,
                              void* d_out, int out_size)
{
    const float* M      = (const float*)d_in[0];
    const float* params = (const float*)d_in[1];
    const int*   kinds  = (const int*)d_in[2];
    float*       out    = (float*)d_out;

    (void)in_sizes; (void)n_in; (void)out_size;

    fused_kernel<<<TOTAL_BLOCKS, 256>>>(M, params, kinds, out);
}

// round 11
// speedup vs baseline: 1.3086x; 1.0344x over previous
#include <cuda_runtime.h>

// Problem constants (fixed by the reference):
//   N_NODES = 2048, N_ELEMS = 4096
//   Output: (N + 2E) x (2E + N) = 10240 x 10240 fp32
#define NN 2048
#define EE 4096
#define WW (2 * EE + NN)   // 10240
#define W4 (WW / 4)        // 2560

// Copy+transpose tiles: 64x64 over M; each writes the kcl copy AND -M^T.
// They come FIRST in the grid so their M reads overlap the fill write stream
// and the kernel tail is pure writes.
#define TP_TILE 64
#define TP_TILES_X (EE / TP_TILE)                     // 64 (e tiles)
#define TP_TILES_Y (NN / TP_TILE)                     // 32 (n tiles)
#define NUM_TP_ITEMS (TP_TILES_X * TP_TILES_Y)        // 2048
// Fill: one block per output row (plain float4 stores, multiple per thread).
#define NUM_FILL_BLOCKS WW                            // 10240
#define TOTAL_BLOCKS (NUM_TP_ITEMS + NUM_FILL_BLOCKS) // 12288

__global__ void __launch_bounds__(256) fused_kernel(
    const float* __restrict__ M,
    const float* __restrict__ params,
    const int* __restrict__ kinds,
    float* __restrict__ out)
{
    const int bid = blockIdx.x;
    const int tid = threadIdx.x;

    if (bid < NUM_TP_ITEMS) {
        // ------------------------------------------------------------------
        // COPY+TRANSPOSE tile, 64x64: read M tile once (4 independent
        // float4 loads per thread, MLP=4), write the kcl copy straight from
        // registers, and the -M^T block via smem transpose.
        //   copy : out[n][e]           = M[n][e]
        //   trans: out[NN + e][2E + n] = -M[n][e]
        // ------------------------------------------------------------------
        __shared__ float tile[TP_TILE][TP_TILE + 1];   // [n_local][e_local]

        const int t  = bid;
        const int et = t % TP_TILES_X;
        const int nt = t / TP_TILES_X;
        const int e0 = et * TP_TILE;
        const int n0 = nt * TP_TILE;

        // Batch all 4 loads first (independent -> 4 outstanding LDG.128).
        float4 m4[4];
        #pragma unroll
        for (int j = 0; j < 4; j++) {
            const int idx  = tid + 256 * j;
            const int lrow = idx >> 4;        // n_local 0..63
            const int lc4  = idx & 15;        // e_local/4 0..15
            m4[j] = reinterpret_cast<const float4*>(
                M + (long)(n0 + lrow) * EE + e0)[lc4];
        }

        // kcl copy stores — straight from registers, coalesced.
        #pragma unroll
        for (int j = 0; j < 4; j++) {
            const int idx  = tid + 256 * j;
            const int lrow = idx >> 4;
            const int lc4  = idx & 15;
            reinterpret_cast<float4*>(
                out)[(long)(n0 + lrow) * W4 + (e0 >> 2) + lc4] = m4[j];
        }

        // Stage for transpose.
        #pragma unroll
        for (int j = 0; j < 4; j++) {
            const int idx  = tid + 256 * j;
            const int lrow = idx >> 4;
            const int lc4  = idx & 15;
            tile[lrow][lc4 * 4 + 0] = m4[j].x;
            tile[lrow][lc4 * 4 + 1] = m4[j].y;
            tile[lrow][lc4 * 4 + 2] = m4[j].z;
            tile[lrow][lc4 * 4 + 3] = m4[j].w;
        }
        __syncthreads();

        // Transposed stores: 4 coalesced float4 per thread.
        #pragma unroll
        for (int j = 0; j < 4; j++) {
            const int idx  = tid + 256 * j;
            const int orow = idx >> 4;        // e_local 0..63
            const int oc4  = idx & 15;        // n_local/4 0..15
            const int nl   = oc4 * 4;
            float4 v;
            v.x = -tile[nl + 0][orow];
            v.y = -tile[nl + 1][orow];
            v.z = -tile[nl + 2][orow];
            v.w = -tile[nl + 3][orow];
            reinterpret_cast<float4*>(
                out + (long)(NN + e0 + orow) * WW + 2 * EE + n0)[oc4] = v;
        }
    } else {
        // ------------------------------------------------------------------
        // FILL path (unchanged from R9/R10 win): block owns one output row.
        // Thread t writes c4 = t + 256*i. Plain cached float4 stores.
        // ------------------------------------------------------------------
        const int row = bid - NUM_TP_ITEMS;
        float4* orow4 = reinterpret_cast<float4*>(out) + (long)row * W4;
        const float4 zero4 = make_float4(0.f, 0.f, 0.f, 0.f);

        if (row < NN) {
            // kcl: [ M | 0 ]. M block (i=0..3) written by tile blocks.
            #pragma unroll
            for (int i = 4; i < 10; i++) {
                orow4[tid + 256 * i] = zero4;
            }
        } else if (row < NN + EE) {
            // kvl: [ 0 | I_E | (-M^T by tiles) ]. Write c4 in [0,2048): i=0..7.
            const int r   = row - NN;
            const int d   = EE + r;          // identity column
            const int dc4 = d >> 2;
            const int dl  = d & 3;
            #pragma unroll
            for (int i = 0; i < 8; i++) {
                const int c4 = tid + 256 * i;
                float4 v = zero4;
                if (c4 == dc4) reinterpret_cast<float*>(&v)[dl] = 1.0f;
                orow4[c4] = v;
            }
        } else {
            // elem: zeros + z diag at col=pos, y diag at col=E+pos.
            const int pos = row - NN - EE;
            const float p = params[pos];
            const int   k = kinds[pos];
            float z = 0.0f;
            if (k == 0)                      z = -p;   // R
            else if (k == 2)                 z = 1.0f; // VC
            else if (k == 3 && !(p > 0.0f))  z = 1.0f; // SW off
            const float y = (k == 0 || k == 1 || (k == 3 && p > 0.0f)) ? 1.0f : 0.0f;

            const int zc4 = pos >> 2;
            const int yc4 = (EE + pos) >> 2;
            const int l   = pos & 3;         // same sub-lane for both diags

            #pragma unroll
            for (int i = 0; i < 10; i++) {
                const int c4 = tid + 256 * i;
                float4 v = zero4;
                if (c4 == zc4) reinterpret_cast<float*>(&v)[l] = z;
                if (c4 == yc4) reinterpret_cast<float*>(&v)[l] = y;
                orow4[c4] = v;
            }
        }
    }
}

extern "C" void kernel_launch(void* const* d_in, const int* in_sizes, int n_in,
                              void* d_out, int out_size)
{
    const float* M      = (const float*)d_in[0];
    const float* params = (const float*)d_in[1];
    const int*   kinds  = (const int*)d_in[2];
    float*       out    = (float*)d_out;

    (void)in_sizes; (void)n_in; (void)out_size;

    fused_kernel<<<TOTAL_BLOCKS, 256>>>(M, params, kinds, out);
}